// round 15
// baseline (speedup 1.0000x reference)
#include <cuda_runtime.h>
#include <cuda_bf16.h>

// Problem constants
#define NRAYS   8192
#define KSEL    4096
#define KSPLIT  128
#define CHUNK   (KSEL / KSPLIT)        // 32 gaussians per block
#define TPB     128
#define NPT     4                      // rays per thread
#define RPB     (TPB * NPT)            // 512 rays per block column
#define NBLK    (NRAYS / RPB)          // 16 columns -> grid (16,128) = 2048 blocks

// s = sqrt(0.5 * log2(e)) : folds exp(-0.5 q) -> 2^(-||W d||^2)
#define SCALE_S 0.8493281132464818f
// integer accumulation scale 2^22 folded into the ex2 exponent (+22.0)
#define INVFIX  (1.0f / 4194304.0f)

// ---- scratch (__device__ globals; zero-initialized, self-resetting) -------
__device__ unsigned long long g_acc[NRAYS];   // fixed-point logit accumulators
__device__ unsigned           g_cnt[NBLK];    // per-column completion tickets

__device__ __forceinline__ float ex2f(float x) {
    float e;
    asm("ex2.approx.ftz.f32 %0, %1;" : "=f"(e) : "f"(x));
    return e;
}
__device__ __forceinline__ int f2i_rni(float x) {
    int v;
    asm("cvt.rni.s32.f32 %0, %1;" : "=r"(v) : "f"(x));
    return v;
}

// ---------------------------------------------------------------------------
// Single fused kernel: grid (NBLK, KSPLIT), 128 threads.
//  Phase 1 (threads 0..31): gather gaussian kbase+tid, W = s*L^{-1},
//    nc = -(W*mu), stage [W(10), nc(4), signmask(int), pad] in shared.
//  Phase 2: scalar FMA mainloop, 4 rays/thread over 32 gaussians.
//    q-chain starts at +22.0 (free 2^22 scale), ex2 -> cvt.rni (cvt pipe)
//    -> sign via LOP3+IADD3 (alu pipe). fma pipe: 14 cyc/pair, nothing else.
//  Phase 3: deterministic integer atomic combine; the last block of each
//    ray column applies sigmoid, writes out, resets state.
// ---------------------------------------------------------------------------
__global__ void __launch_bounds__(TPB)
fused_kernel(const float* __restrict__ org,
             const float* __restrict__ dir,
             const float* __restrict__ emb,
             const float* __restrict__ chol,
             const float* __restrict__ labels,
             const int*   __restrict__ idx,
             float* __restrict__ out)
{
    __shared__ float4 sm[CHUNK * 4];   // 2 KB
    __shared__ int s_last;

    const int tid   = threadIdx.x;
    const int nbase = blockIdx.x * RPB;
    const int kbase = blockIdx.y * CHUNK;

    // ---- Phase 1: per-gaussian setup (threads 0..31) ----
    if (tid < CHUNK) {
        int m = __ldg(idx + kbase + tid);
        const float4* c4 = reinterpret_cast<const float4*>(chol) + (size_t)m * 4;
        float4 r0 = c4[0], r1 = c4[1], r2 = c4[2], r3 = c4[3];
        float L00 = r0.x;
        float L10 = r1.x, L11 = r1.y;
        float L20 = r2.x, L21 = r2.y, L22 = r2.z;
        float L30 = r3.x, L31 = r3.y, L32 = r3.z, L33 = r3.w;

        float i0 = 1.0f / L00, i1 = 1.0f / L11, i2 = 1.0f / L22, i3 = 1.0f / L33;

        float U00 = i0, U11 = i1, U22 = i2, U33 = i3;
        float U10 = -(L10 * U00) * i1;
        float U20 = -(L20 * U00 + L21 * U10) * i2;
        float U21 = -(L21 * U11) * i2;
        float U30 = -(L30 * U00 + L31 * U10 + L32 * U20) * i3;
        float U31 = -(L31 * U11 + L32 * U21) * i3;
        float U32 = -(L32 * U22) * i3;

        const float s = SCALE_S;
        U00 *= s; U10 *= s; U11 *= s; U20 *= s; U21 *= s; U22 *= s;
        U30 *= s; U31 *= s; U32 *= s; U33 *= s;

        float4 mu = reinterpret_cast<const float4*>(emb)[m];
        float nc0 = -(U00 * mu.x);
        float nc1 = -(U10 * mu.x + U11 * mu.y);
        float nc2 = -(U20 * mu.x + U21 * mu.y + U22 * mu.z);
        float nc3 = -(U30 * mu.x + U31 * mu.y + U32 * mu.z + U33 * mu.w);
        float lab = __ldg(labels + m);
        // label as integer mask: -1 (all ones) for lab=-1, 0 for lab=+1
        int m32 = (lab < 0.0f) ? -1 : 0;

        sm[tid * 4 + 0] = make_float4(U00, U10, U11, U20);
        sm[tid * 4 + 1] = make_float4(U21, U22, U30, U31);
        sm[tid * 4 + 2] = make_float4(U32, U33, nc0, nc1);
        sm[tid * 4 + 3] = make_float4(nc2, nc3, __int_as_float(m32), 0.0f);
    }

    // ---- load rays (independent of shared) ----
    float p0[NPT], p1[NPT], p2[NPT], p3[NPT];
    int   acc[NPT];
    const float2* o2 = reinterpret_cast<const float2*>(org);
    const float2* d2 = reinterpret_cast<const float2*>(dir);
#pragma unroll
    for (int j = 0; j < NPT; j++) {
        int n = nbase + tid + j * TPB;
        float2 o = o2[n];
        float2 d = d2[n];
        p0[j] = o.x; p1[j] = o.y; p2[j] = d.x; p3[j] = d.y;
        acc[j] = 0;
    }
    __syncthreads();

    // ---- Phase 2: scalar FMA mainloop ----
#pragma unroll 4
    for (int kk = 0; kk < CHUNK; kk++) {
        float4 f0 = sm[kk * 4 + 0];   // U00 U10 U11 U20
        float4 f1 = sm[kk * 4 + 1];   // U21 U22 U30 U31
        float4 f2 = sm[kk * 4 + 2];   // U32 U33 nc0 nc1
        float4 f3 = sm[kk * 4 + 3];   // nc2 nc3 m32 pad
        int m32  = __float_as_int(f3.z);
        int negm = -m32;              // 1 if label -1, else 0
#pragma unroll
        for (int j = 0; j < NPT; j++) {
            float y0 = __fmaf_rn(f0.x, p0[j], f2.z);
            float y1 = __fmaf_rn(f0.y, p0[j], f2.w);
            y1 = __fmaf_rn(f0.z, p1[j], y1);
            float y2 = __fmaf_rn(f0.w, p0[j], f3.x);
            y2 = __fmaf_rn(f1.x, p1[j], y2);
            y2 = __fmaf_rn(f1.y, p2[j], y2);
            float y3 = __fmaf_rn(f1.z, p0[j], f3.y);
            y3 = __fmaf_rn(f1.w, p1[j], y3);
            y3 = __fmaf_rn(f2.x, p2[j], y3);
            y3 = __fmaf_rn(f2.y, p3[j], y3);
            // 22 - q : the +22 folds the 2^22 integer scale into ex2 for free
            float qn = __fmaf_rn(y0, -y0, 22.0f);
            qn = __fmaf_rn(y1, -y1, qn);
            qn = __fmaf_rn(y2, -y2, qn);
            qn = __fmaf_rn(y3, -y3, qn);
            int v = f2i_rni(ex2f(qn));            // e * 2^22, cvt pipe
            acc[j] = acc[j] + (v ^ m32) + negm;   // LOP3 + IADD3, alu pipe
        }
    }

    // ---- Phase 3: deterministic integer combine ----
#pragma unroll
    for (int j = 0; j < NPT; j++) {
        int n = nbase + tid + j * TPB;
        atomicAdd(&g_acc[n], (unsigned long long)(long long)acc[j]);
    }
    __threadfence();
    __syncthreads();

    if (tid == 0) {
        unsigned old = atomicAdd(&g_cnt[blockIdx.x], 1u);
        s_last = (old == KSPLIT - 1) ? 1 : 0;
    }
    __syncthreads();

    if (s_last) {
        __threadfence();   // acquire: see all columns' g_acc updates
#pragma unroll
        for (int j = 0; j < NPT; j++) {
            int n = nbase + tid + j * TPB;
            long long v = (long long)__ldcg(&g_acc[n]);
            float s = (float)v * INVFIX;
            float e = ex2f(-s * 1.4426950408889634f);
            out[n] = 1.0f / (1.0f + e);
            g_acc[n] = 0ull;            // reset for next graph replay
        }
        if (tid == 0) g_cnt[blockIdx.x] = 0u;
    }
}

// ---------------------------------------------------------------------------
extern "C" void kernel_launch(void* const* d_in, const int* in_sizes, int n_in,
                              void* d_out, int out_size)
{
    const float* origins    = (const float*)d_in[0];
    const float* directions = (const float*)d_in[1];
    const float* embeddings = (const float*)d_in[2];
    const float* chol       = (const float*)d_in[3];
    const float* labels     = (const float*)d_in[4];
    const int*   idx        = (const int*)  d_in[5];
    float* out = (float*)d_out;

    fused_kernel<<<dim3(NBLK, KSPLIT), TPB>>>(origins, directions, embeddings,
                                              chol, labels, idx, out);
}

// round 16
// speedup vs baseline: 1.0874x; 1.0874x over previous
#include <cuda_runtime.h>
#include <cuda_bf16.h>

// Problem constants
#define NRAYS   8192
#define KSEL    4096
#define KSPLIT  128
#define CHUNK   (KSEL / KSPLIT)        // 32 gaussians per block
#define TPB     128
#define NPT     4                      // rays per thread
#define RPB     (TPB * NPT)            // 512 rays per block column
#define NBLK    (NRAYS / RPB)          // 16 columns -> grid (16,128) = 2048 blocks

// s = sqrt(0.5 * log2(e)) : folds exp(-0.5 q) -> 2^(-||W d||^2)
#define SCALE_S 0.8493281132464818f
#define FIXSCALE 1073741824.0          // 2^30 fixed-point scale (double)
#define INVFIX   (1.0f / 1073741824.0f)

// ---- scratch (__device__ globals; zero-initialized, self-resetting) -------
__device__ unsigned long long g_acc[NRAYS];   // fixed-point logit accumulators
__device__ unsigned           g_cnt[NBLK];    // per-column completion tickets

__device__ __forceinline__ float ex2f(float x) {
    float e;
    asm("ex2.approx.ftz.f32 %0, %1;" : "=f"(e) : "f"(x));
    return e;
}

// accumulate via multiplier-immediate FFMA (rt_SMSP=1 on sm_103a)
__device__ __forceinline__ void acc_imm(float& acc, float e) {
    asm("fma.rn.f32 %0, %1, 0f3F800000, %0;" : "+f"(acc) : "f"(e));
}

// ---------------------------------------------------------------------------
// Single fused kernel: grid (NBLK, KSPLIT), 128 threads  [R14 config].
//  Phase 1 (threads 0..31): gather gaussian kbase+tid, W = s*L^{-1},
//    nc = -(W*mu), stage [W(10), nc(4), signmask, pad] in shared.
//  Phase 2: scalar FMA mainloop, 4 rays/thread over 32 gaussians.
//    Label applied as sign-bit XOR (LOP3, alu pipe) + FFMA-imm accumulate.
//    Fully unrolled (body ~8 KB, fits I$ L0+L1.5).
//  Phase 3: deterministic integer fixed-point atomic combine; the last
//    block of each ray column applies sigmoid, writes out, resets state.
// ---------------------------------------------------------------------------
__global__ void __launch_bounds__(TPB)
fused_kernel(const float* __restrict__ org,
             const float* __restrict__ dir,
             const float* __restrict__ emb,
             const float* __restrict__ chol,
             const float* __restrict__ labels,
             const int*   __restrict__ idx,
             float* __restrict__ out)
{
    __shared__ float4 sm[CHUNK * 4];   // 2 KB
    __shared__ int s_last;

    const int tid   = threadIdx.x;
    const int nbase = blockIdx.x * RPB;
    const int kbase = blockIdx.y * CHUNK;

    // ---- Phase 1: per-gaussian setup (threads 0..31) ----
    if (tid < CHUNK) {
        int m = __ldg(idx + kbase + tid);
        const float4* c4 = reinterpret_cast<const float4*>(chol) + (size_t)m * 4;
        float4 r0 = c4[0], r1 = c4[1], r2 = c4[2], r3 = c4[3];
        float L00 = r0.x;
        float L10 = r1.x, L11 = r1.y;
        float L20 = r2.x, L21 = r2.y, L22 = r2.z;
        float L30 = r3.x, L31 = r3.y, L32 = r3.z, L33 = r3.w;

        float i0 = 1.0f / L00, i1 = 1.0f / L11, i2 = 1.0f / L22, i3 = 1.0f / L33;

        float U00 = i0, U11 = i1, U22 = i2, U33 = i3;
        float U10 = -(L10 * U00) * i1;
        float U20 = -(L20 * U00 + L21 * U10) * i2;
        float U21 = -(L21 * U11) * i2;
        float U30 = -(L30 * U00 + L31 * U10 + L32 * U20) * i3;
        float U31 = -(L31 * U11 + L32 * U21) * i3;
        float U32 = -(L32 * U22) * i3;

        const float s = SCALE_S;
        U00 *= s; U10 *= s; U11 *= s; U20 *= s; U21 *= s; U22 *= s;
        U30 *= s; U31 *= s; U32 *= s; U33 *= s;

        float4 mu = reinterpret_cast<const float4*>(emb)[m];
        float nc0 = -(U00 * mu.x);
        float nc1 = -(U10 * mu.x + U11 * mu.y);
        float nc2 = -(U20 * mu.x + U21 * mu.y + U22 * mu.z);
        float nc3 = -(U30 * mu.x + U31 * mu.y + U32 * mu.z + U33 * mu.w);
        float lab = __ldg(labels + m);
        // store label as a sign mask: 0x80000000 for -1, 0 for +1
        unsigned smask = (lab < 0.0f) ? 0x80000000u : 0u;

        sm[tid * 4 + 0] = make_float4(U00, U10, U11, U20);
        sm[tid * 4 + 1] = make_float4(U21, U22, U30, U31);
        sm[tid * 4 + 2] = make_float4(U32, U33, nc0, nc1);
        sm[tid * 4 + 3] = make_float4(nc2, nc3, __uint_as_float(smask), 0.0f);
    }

    // ---- load rays (independent of shared) ----
    float p0[NPT], p1[NPT], p2[NPT], p3[NPT], acc[NPT];
    const float2* o2 = reinterpret_cast<const float2*>(org);
    const float2* d2 = reinterpret_cast<const float2*>(dir);
#pragma unroll
    for (int j = 0; j < NPT; j++) {
        int n = nbase + tid + j * TPB;
        float2 o = o2[n];
        float2 d = d2[n];
        p0[j] = o.x; p1[j] = o.y; p2[j] = d.x; p3[j] = d.y;
        acc[j] = 0.0f;
    }
    __syncthreads();

    // ---- Phase 2: scalar FMA mainloop (fully unrolled) ----
#pragma unroll 8
    for (int kk = 0; kk < CHUNK; kk++) {
        float4 f0 = sm[kk * 4 + 0];   // U00 U10 U11 U20
        float4 f1 = sm[kk * 4 + 1];   // U21 U22 U30 U31
        float4 f2 = sm[kk * 4 + 2];   // U32 U33 nc0 nc1
        float4 f3 = sm[kk * 4 + 3];   // nc2 nc3 smask pad
        unsigned smask = __float_as_uint(f3.z);
#pragma unroll
        for (int j = 0; j < NPT; j++) {
            float y0 = __fmaf_rn(f0.x, p0[j], f2.z);
            float y1 = __fmaf_rn(f0.y, p0[j], f2.w);
            y1 = __fmaf_rn(f0.z, p1[j], y1);
            float y2 = __fmaf_rn(f0.w, p0[j], f3.x);
            y2 = __fmaf_rn(f1.x, p1[j], y2);
            y2 = __fmaf_rn(f1.y, p2[j], y2);
            float y3 = __fmaf_rn(f1.z, p0[j], f3.y);
            y3 = __fmaf_rn(f1.w, p1[j], y3);
            y3 = __fmaf_rn(f2.x, p2[j], y3);
            y3 = __fmaf_rn(f2.y, p3[j], y3);
            float qn = -(y0 * y0);
            qn = __fmaf_rn(y1, -y1, qn);
            qn = __fmaf_rn(y2, -y2, qn);
            qn = __fmaf_rn(y3, -y3, qn);
            float e = ex2f(qn);
            // sign-apply label on the ALU pipe (LOP3), accumulate via FFMA-imm (rt1)
            float es = __uint_as_float(__float_as_uint(e) ^ smask);
            acc_imm(acc[j], es);
        }
    }

    // ---- Phase 3: deterministic integer combine ----
#pragma unroll
    for (int j = 0; j < NPT; j++) {
        int n = nbase + tid + j * TPB;
        long long v = (long long)((double)acc[j] * FIXSCALE);  // order-free integer sum
        atomicAdd(&g_acc[n], (unsigned long long)v);
    }
    __threadfence();
    __syncthreads();

    if (tid == 0) {
        unsigned old = atomicAdd(&g_cnt[blockIdx.x], 1u);
        s_last = (old == KSPLIT - 1) ? 1 : 0;
    }
    __syncthreads();

    if (s_last) {
        __threadfence();   // acquire: see all columns' g_acc updates
#pragma unroll
        for (int j = 0; j < NPT; j++) {
            int n = nbase + tid + j * TPB;
            long long v = (long long)__ldcg(&g_acc[n]);
            float s = (float)v * INVFIX;
            float e = ex2f(-s * 1.4426950408889634f);
            out[n] = 1.0f / (1.0f + e);
            g_acc[n] = 0ull;            // reset for next graph replay
        }
        if (tid == 0) g_cnt[blockIdx.x] = 0u;
    }
}

// ---------------------------------------------------------------------------
extern "C" void kernel_launch(void* const* d_in, const int* in_sizes, int n_in,
                              void* d_out, int out_size)
{
    const float* origins    = (const float*)d_in[0];
    const float* directions = (const float*)d_in[1];
    const float* embeddings = (const float*)d_in[2];
    const float* chol       = (const float*)d_in[3];
    const float* labels     = (const float*)d_in[4];
    const int*   idx        = (const int*)  d_in[5];
    float* out = (float*)d_out;

    fused_kernel<<<dim3(NBLK, KSPLIT), TPB>>>(origins, directions, embeddings,
                                              chol, labels, idx, out);
}

// round 17
// speedup vs baseline: 1.1745x; 1.0801x over previous
#include <cuda_runtime.h>
#include <cuda_bf16.h>

// Problem constants
#define NRAYS   8192
#define KSEL    4096
#define KSPLIT  128
#define CHUNK   (KSEL / KSPLIT)        // 32 gaussians per block
#define TPB     128
#define NPT     4                      // rays per thread
#define RPB     (TPB * NPT)            // 512 rays per block column
#define NBLK    (NRAYS / RPB)          // 16 columns -> grid (16,128) = 2048 blocks

// s = sqrt(0.5 * log2(e)) : folds exp(-0.5 q) -> 2^(-||W d||^2)
#define SCALE_S 0.8493281132464818f
#define FIXSCALE 1073741824.0          // 2^30 fixed-point scale (double)
#define INVFIX   (1.0f / 1073741824.0f)

// ---- scratch (__device__ globals; zero-initialized, self-resetting) -------
__device__ unsigned long long g_acc[NRAYS];   // fixed-point logit accumulators
__device__ unsigned           g_cnt[NBLK];    // per-column completion tickets

__device__ __forceinline__ float ex2f(float x) {
    float e;
    asm("ex2.approx.ftz.f32 %0, %1;" : "=f"(e) : "f"(x));
    return e;
}

// accumulate via multiplier-immediate FFMA (rt_SMSP=1 on sm_103a)
__device__ __forceinline__ void acc_imm(float& acc, float e) {
    asm("fma.rn.f32 %0, %1, 0f3F800000, %0;" : "+f"(acc) : "f"(e));
}

// ---------------------------------------------------------------------------
// Single fused kernel: grid (NBLK, KSPLIT), 128 threads  [R14, measured best].
//  Phase 1 (threads 0..31): gather gaussian kbase+tid, W = s*L^{-1},
//    nc = -(W*mu), stage [W(10), nc(4), signmask, pad] in shared.
//  Phase 2: scalar FMA mainloop, 4 rays/thread over 32 gaussians.
//    Label applied as sign-bit XOR (LOP3, alu pipe) + FFMA-imm accumulate.
//  Phase 3: deterministic integer fixed-point atomic combine; the last
//    block of each ray column applies sigmoid, writes out, resets state.
// ---------------------------------------------------------------------------
__global__ void __launch_bounds__(TPB)
fused_kernel(const float* __restrict__ org,
             const float* __restrict__ dir,
             const float* __restrict__ emb,
             const float* __restrict__ chol,
             const float* __restrict__ labels,
             const int*   __restrict__ idx,
             float* __restrict__ out)
{
    __shared__ float4 sm[CHUNK * 4];   // 2 KB
    __shared__ int s_last;

    const int tid   = threadIdx.x;
    const int nbase = blockIdx.x * RPB;
    const int kbase = blockIdx.y * CHUNK;

    // ---- Phase 1: per-gaussian setup (threads 0..31) ----
    if (tid < CHUNK) {
        int m = __ldg(idx + kbase + tid);
        const float4* c4 = reinterpret_cast<const float4*>(chol) + (size_t)m * 4;
        float4 r0 = c4[0], r1 = c4[1], r2 = c4[2], r3 = c4[3];
        float L00 = r0.x;
        float L10 = r1.x, L11 = r1.y;
        float L20 = r2.x, L21 = r2.y, L22 = r2.z;
        float L30 = r3.x, L31 = r3.y, L32 = r3.z, L33 = r3.w;

        float i0 = 1.0f / L00, i1 = 1.0f / L11, i2 = 1.0f / L22, i3 = 1.0f / L33;

        float U00 = i0, U11 = i1, U22 = i2, U33 = i3;
        float U10 = -(L10 * U00) * i1;
        float U20 = -(L20 * U00 + L21 * U10) * i2;
        float U21 = -(L21 * U11) * i2;
        float U30 = -(L30 * U00 + L31 * U10 + L32 * U20) * i3;
        float U31 = -(L31 * U11 + L32 * U21) * i3;
        float U32 = -(L32 * U22) * i3;

        const float s = SCALE_S;
        U00 *= s; U10 *= s; U11 *= s; U20 *= s; U21 *= s; U22 *= s;
        U30 *= s; U31 *= s; U32 *= s; U33 *= s;

        float4 mu = reinterpret_cast<const float4*>(emb)[m];
        float nc0 = -(U00 * mu.x);
        float nc1 = -(U10 * mu.x + U11 * mu.y);
        float nc2 = -(U20 * mu.x + U21 * mu.y + U22 * mu.z);
        float nc3 = -(U30 * mu.x + U31 * mu.y + U32 * mu.z + U33 * mu.w);
        float lab = __ldg(labels + m);
        // store label as a sign mask: 0x80000000 for -1, 0 for +1
        unsigned smask = (lab < 0.0f) ? 0x80000000u : 0u;

        sm[tid * 4 + 0] = make_float4(U00, U10, U11, U20);
        sm[tid * 4 + 1] = make_float4(U21, U22, U30, U31);
        sm[tid * 4 + 2] = make_float4(U32, U33, nc0, nc1);
        sm[tid * 4 + 3] = make_float4(nc2, nc3, __uint_as_float(smask), 0.0f);
    }

    // ---- load rays (independent of shared) ----
    float p0[NPT], p1[NPT], p2[NPT], p3[NPT], acc[NPT];
    const float2* o2 = reinterpret_cast<const float2*>(org);
    const float2* d2 = reinterpret_cast<const float2*>(dir);
#pragma unroll
    for (int j = 0; j < NPT; j++) {
        int n = nbase + tid + j * TPB;
        float2 o = o2[n];
        float2 d = d2[n];
        p0[j] = o.x; p1[j] = o.y; p2[j] = d.x; p3[j] = d.y;
        acc[j] = 0.0f;
    }
    __syncthreads();

    // ---- Phase 2: scalar FMA mainloop ----
#pragma unroll 4
    for (int kk = 0; kk < CHUNK; kk++) {
        float4 f0 = sm[kk * 4 + 0];   // U00 U10 U11 U20
        float4 f1 = sm[kk * 4 + 1];   // U21 U22 U30 U31
        float4 f2 = sm[kk * 4 + 2];   // U32 U33 nc0 nc1
        float4 f3 = sm[kk * 4 + 3];   // nc2 nc3 smask pad
        unsigned smask = __float_as_uint(f3.z);
#pragma unroll
        for (int j = 0; j < NPT; j++) {
            float y0 = __fmaf_rn(f0.x, p0[j], f2.z);
            float y1 = __fmaf_rn(f0.y, p0[j], f2.w);
            y1 = __fmaf_rn(f0.z, p1[j], y1);
            float y2 = __fmaf_rn(f0.w, p0[j], f3.x);
            y2 = __fmaf_rn(f1.x, p1[j], y2);
            y2 = __fmaf_rn(f1.y, p2[j], y2);
            float y3 = __fmaf_rn(f1.z, p0[j], f3.y);
            y3 = __fmaf_rn(f1.w, p1[j], y3);
            y3 = __fmaf_rn(f2.x, p2[j], y3);
            y3 = __fmaf_rn(f2.y, p3[j], y3);
            float qn = -(y0 * y0);
            qn = __fmaf_rn(y1, -y1, qn);
            qn = __fmaf_rn(y2, -y2, qn);
            qn = __fmaf_rn(y3, -y3, qn);
            float e = ex2f(qn);
            // sign-apply label on the ALU pipe (LOP3), accumulate via FFMA-imm (rt1)
            float es = __uint_as_float(__float_as_uint(e) ^ smask);
            acc_imm(acc[j], es);
        }
    }

    // ---- Phase 3: deterministic integer combine ----
#pragma unroll
    for (int j = 0; j < NPT; j++) {
        int n = nbase + tid + j * TPB;
        long long v = (long long)((double)acc[j] * FIXSCALE);  // order-free integer sum
        atomicAdd(&g_acc[n], (unsigned long long)v);
    }
    __threadfence();
    __syncthreads();

    if (tid == 0) {
        unsigned old = atomicAdd(&g_cnt[blockIdx.x], 1u);
        s_last = (old == KSPLIT - 1) ? 1 : 0;
    }
    __syncthreads();

    if (s_last) {
        __threadfence();   // acquire: see all columns' g_acc updates
#pragma unroll
        for (int j = 0; j < NPT; j++) {
            int n = nbase + tid + j * TPB;
            long long v = (long long)__ldcg(&g_acc[n]);
            float s = (float)v * INVFIX;
            float e = ex2f(-s * 1.4426950408889634f);
            out[n] = 1.0f / (1.0f + e);
            g_acc[n] = 0ull;            // reset for next graph replay
        }
        if (tid == 0) g_cnt[blockIdx.x] = 0u;
    }
}

// ---------------------------------------------------------------------------
extern "C" void kernel_launch(void* const* d_in, const int* in_sizes, int n_in,
                              void* d_out, int out_size)
{
    const float* origins    = (const float*)d_in[0];
    const float* directions = (const float*)d_in[1];
    const float* embeddings = (const float*)d_in[2];
    const float* chol       = (const float*)d_in[3];
    const float* labels     = (const float*)d_in[4];
    const int*   idx        = (const int*)  d_in[5];
    float* out = (float*)d_out;

    fused_kernel<<<dim3(NBLK, KSPLIT), TPB>>>(origins, directions, embeddings,
                                              chol, labels, idx, out);
}